// round 2
// baseline (speedup 1.0000x reference)
#include <cuda_runtime.h>
#include <math.h>

#define N_E     8192
#define C_DIM   256
#define BATCH   32
#define HW      1024
#define N_ROWS  (BATCH * HW)            // 32768
#define ZQ_ELEMS (BATCH * C_DIM * HW)   // 8388608

// ---- scratch (no allocations allowed) ----
__device__ float  g_Wt[C_DIM * N_E];    // Wt[k][e] = W[e][k]  (8 MB)
__device__ float  g_znorm[N_ROWS];      // |z_n|^2 (fp32, reference-equivalent binade)
__device__ int    g_idx[N_ROWS];
__device__ int    g_hist[N_E];
__device__ double g_loss;

// ---------------------------------------------------------------------------
// 0) zero per-launch accumulators (graph replays must be deterministic)
// ---------------------------------------------------------------------------
__global__ void k_zero() {
    int i = blockIdx.x * blockDim.x + threadIdx.x;
    if (i < N_E) g_hist[i] = 0;
    if (i == 0)  g_loss = 0.0;
}

// ---------------------------------------------------------------------------
// 1) transpose W (8192 x 256) -> Wt (256 x 8192), tiled 32x32
// ---------------------------------------------------------------------------
__global__ void k_transpose(const float* __restrict__ W) {
    __shared__ float tile[32][33];
    int e0 = blockIdx.x * 32;
    int k0 = blockIdx.y * 32;
    int tx = threadIdx.x, ty = threadIdx.y;
    #pragma unroll
    for (int j = 0; j < 4; j++)
        tile[ty + 8 * j][tx] = W[(size_t)(e0 + ty + 8 * j) * C_DIM + k0 + tx];
    __syncthreads();
    #pragma unroll
    for (int j = 0; j < 4; j++)
        g_Wt[(size_t)(k0 + ty + 8 * j) * N_E + e0 + tx] = tile[tx][ty + 8 * j];
}

// ---------------------------------------------------------------------------
// 2) znorm[n] = |z_n|^2 : one thread per row, coalesced across hw
// ---------------------------------------------------------------------------
__global__ void k_znorm(const float* __restrict__ z) {
    int n = blockIdx.x * blockDim.x + threadIdx.x;   // n = b*1024 + hw
    if (n >= N_ROWS) return;
    int b = n >> 10, hw = n & 1023;
    const float* p = z + (size_t)b * C_DIM * HW + hw;
    float s = 0.f;
    #pragma unroll 8
    for (int c = 0; c < C_DIM; c++) {
        float v = p[(size_t)c * HW];
        s += v * v;
    }
    g_znorm[n] = s;
}

// ---------------------------------------------------------------------------
// 3) main kernel: argmin_e fl(|z|^2 - 2 * (z . w_e))   [matches reference's
//    fp32 rounding: |w|^2 provably vanishes under the +|z|^2 fp32 add]
//    GEMM tiling: BM=128 rows x BE=128 codes x BK=32, 256 threads, 8x8/thread.
// ---------------------------------------------------------------------------
#define BM 128
#define BE 128
#define BK 32

__global__ __launch_bounds__(256, 2)
void k_argmin(const float* __restrict__ z) {
    __shared__ float As[BK][BM];
    __shared__ float Bs[BK][BE];

    int tid = threadIdx.x;
    int tx = tid & 15, ty = tid >> 4;       // 16 x 16
    int n0 = blockIdx.x * BM;               // row-tile start (stays inside one b)
    int b   = n0 >> 10;
    int hw0 = n0 & 1023;
    const float* zb = z + (size_t)b * C_DIM * HW + hw0;

    // per-row |z|^2 for this thread's 8 rows
    float Arow[8];
    #pragma unroll
    for (int i = 0; i < 8; i++) Arow[i] = g_znorm[n0 + ty * 8 + i];

    float bestv[8];
    int   besti[8];
    #pragma unroll
    for (int i = 0; i < 8; i++) { bestv[i] = 3.4e38f; besti[i] = 0; }

    float acc[8][8];

    for (int e0 = 0; e0 < N_E; e0 += BE) {
        #pragma unroll
        for (int i = 0; i < 8; i++)
            #pragma unroll
            for (int j = 0; j < 8; j++) acc[i][j] = 0.f;

        for (int k0 = 0; k0 < C_DIM; k0 += BK) {
            // A tile: z is (B,C,H,W) so fixed channel -> contiguous rows: coalesced
            #pragma unroll
            for (int i = 0; i < 4; i++) {
                int idx = i * 256 + tid;      // float4 slot 0..1023
                int k   = idx >> 5;           // 0..31
                int r4  = (idx & 31) * 4;     // 0..124
                float4 v = *reinterpret_cast<const float4*>(zb + (size_t)(k0 + k) * HW + r4);
                *reinterpret_cast<float4*>(&As[k][r4]) = v;
            }
            // B tile from pre-transposed Wt[k][e]: coalesced
            const float* wb = g_Wt + (size_t)k0 * N_E + e0;
            #pragma unroll
            for (int i = 0; i < 4; i++) {
                int idx = i * 256 + tid;
                int k   = idx >> 5;
                int c4  = (idx & 31) * 4;
                float4 v = *reinterpret_cast<const float4*>(wb + (size_t)k * N_E + c4);
                *reinterpret_cast<float4*>(&Bs[k][c4]) = v;
            }
            __syncthreads();

            #pragma unroll
            for (int k = 0; k < BK; k++) {
                float a[8], bv[8];
                *reinterpret_cast<float4*>(&a[0])  = *reinterpret_cast<float4*>(&As[k][ty * 8]);
                *reinterpret_cast<float4*>(&a[4])  = *reinterpret_cast<float4*>(&As[k][ty * 8 + 4]);
                *reinterpret_cast<float4*>(&bv[0]) = *reinterpret_cast<float4*>(&Bs[k][tx * 8]);
                *reinterpret_cast<float4*>(&bv[4]) = *reinterpret_cast<float4*>(&Bs[k][tx * 8 + 4]);
                #pragma unroll
                for (int i = 0; i < 8; i++)
                    #pragma unroll
                    for (int j = 0; j < 8; j++)
                        acc[i][j] += a[i] * bv[j];
            }
            __syncthreads();
        }

        // fold this code tile into the running argmin.
        // score = fl(A - 2*dot): -2*acc product is exact (x2 = exponent bump),
        // so FFMA(-2,acc,A) == fl(A - 2*acc) == reference's rounding.
        #pragma unroll
        for (int j = 0; j < 8; j++) {
            int e = e0 + tx * 8 + j;
            #pragma unroll
            for (int i = 0; i < 8; i++) {
                float s = fmaf(-2.0f, acc[i][j], Arow[i]);
                if (s < bestv[i]) { bestv[i] = s; besti[i] = e; }  // strict <: lowest e wins
            }
        }
    }

    // reduce argmin across the 16 tx lanes (xor shuffle stays inside 16-lane group)
    #pragma unroll
    for (int i = 0; i < 8; i++) {
        float v = bestv[i]; int id = besti[i];
        #pragma unroll
        for (int o = 8; o; o >>= 1) {
            float ov = __shfl_xor_sync(0xFFFFFFFFu, v, o);
            int   oi = __shfl_xor_sync(0xFFFFFFFFu, id, o);
            if (ov < v || (ov == v && oi < id)) { v = ov; id = oi; }
        }
        if (tx == 0) {
            int row = ty * 8 + i;
            g_idx[n0 + row] = id;
            atomicAdd(&g_hist[id], 1);
        }
    }
}

// ---------------------------------------------------------------------------
// 4) epilogue: z_q gather (already in (B,C,H,W)), loss partials, index output
// ---------------------------------------------------------------------------
__global__ void k_epilogue(const float* __restrict__ z, float* __restrict__ out) {
    int bid = blockIdx.x;
    int b = bid >> 8, c = bid & 255;
    int tid = threadIdx.x;
    const float* wtc = g_Wt + (size_t)c * N_E;   // W[.][c], 32 KB slab -> L2 friendly
    float lsum = 0.f;
    #pragma unroll
    for (int it = 0; it < 4; it++) {
        int hw = it * 256 + tid;
        int n  = b * HW + hw;
        int id = g_idx[n];
        float wv = wtc[id];
        size_t off = (size_t)b * C_DIM * HW + (size_t)c * HW + hw;
        float zv = z[off];
        out[off] = wv;                            // z_q (straight-through forward value)
        float d = wv - zv;
        lsum += d * d;
        if (c == 0) out[ZQ_ELEMS + 1 + n] = (float)id;   // index output
    }
    __shared__ float red[256];
    red[tid] = lsum;
    __syncthreads();
    for (int s = 128; s; s >>= 1) { if (tid < s) red[tid] += red[tid + s]; __syncthreads(); }
    if (tid == 0) atomicAdd(&g_loss, (double)red[0]);
}

// ---------------------------------------------------------------------------
// 5) final: loss scalar + perplexity
// ---------------------------------------------------------------------------
__global__ void k_final(float* __restrict__ out) {
    __shared__ float red[256];
    int tid = threadIdx.x;
    float s = 0.f;
    for (int i = tid; i < N_E; i += 256) {
        float e = (float)g_hist[i] * (1.0f / (float)N_ROWS);
        s += e * logf(e + 1e-10f);
    }
    red[tid] = s;
    __syncthreads();
    for (int st = 128; st; st >>= 1) { if (tid < st) red[tid] += red[tid + st]; __syncthreads(); }
    if (tid == 0) {
        // loss = mean((zq-z)^2) + beta*mean((zq-z)^2) = 1.25 * mean
        out[ZQ_ELEMS] = 1.25f * (float)(g_loss / (double)ZQ_ELEMS);
        out[ZQ_ELEMS + 1 + N_ROWS] = expf(-red[0]);
    }
}

// ---------------------------------------------------------------------------
extern "C" void kernel_launch(void* const* d_in, const int* in_sizes, int n_in,
                              void* d_out, int out_size) {
    const float* z = (const float*)d_in[0];   // (32,256,32,32) f32
    const float* W = (const float*)d_in[1];   // (8192,256) f32
    float* out = (float*)d_out;

    k_zero<<<(N_E + 255) / 256, 256>>>();
    {
        dim3 g(N_E / 32, C_DIM / 32), blk(32, 8);
        k_transpose<<<g, blk>>>(W);
    }
    k_znorm<<<N_ROWS / 256, 256>>>(z);
    k_argmin<<<N_ROWS / BM, 256>>>(z);
    k_epilogue<<<BATCH * C_DIM, 256>>>(z, out);
    k_final<<<1, 256>>>(out);
}

// round 4
// speedup vs baseline: 2.6280x; 2.6280x over previous
#include <cuda_runtime.h>
#include <cuda_bf16.h>
#include <math.h>
#include <stdint.h>

#define N_E     8192
#define C_DIM   256
#define BATCH   32
#define HW      1024
#define N_ROWS  (BATCH * HW)            // 32768
#define ZQ_ELEMS (BATCH * C_DIM * HW)   // 8388608

#define BM   128                        // rows per CTA
#define KP   768                        // virtual K: [hi(256) | lo(256) | hi(256)]
#define NCHUNK 12                       // 64-k chunks per e-tile (768/64)
#define NETILE 64                       // e-tiles of 128 codes

// smem offsets (dynamic)
#define A_HI   0                        // [256][128] bf16, swizzled  (64KB)
#define A_LO   65536                    // (64KB)
#define W_OFF  131072                   // two 16KB buffers [128][64] bf16
#define SRED   131072                   // alias of W buffers (used after GEMM)
#define SMEM_BYTES (131072 + 2 * 16384) // 163840

// ---- scratch (no allocations allowed) ----
__device__ float g_Wt[C_DIM * N_E];                       // Wt[k][e] for epilogue
__device__ __align__(16) __nv_bfloat16 g_Wb[N_E * KP];    // [e][hi|lo|hi]  12.6MB
__device__ float g_znorm[N_ROWS];
__device__ int   g_idx[N_ROWS];
__device__ int   g_hist[N_E];
__device__ double g_loss;

// =========================== helpers ===================================
__device__ __forceinline__ uint32_t smem_u32(const void* p) {
    uint32_t a;
    asm("{ .reg .u64 t; cvta.to.shared.u64 t, %1; cvt.u32.u64 %0, t; }" : "=r"(a) : "l"(p));
    return a;
}
__device__ __forceinline__ void ldsm4(uint32_t* r, uint32_t addr) {
    asm volatile("ldmatrix.sync.aligned.m8n8.x4.shared.b16 {%0,%1,%2,%3}, [%4];"
                 : "=r"(r[0]), "=r"(r[1]), "=r"(r[2]), "=r"(r[3]) : "r"(addr));
}
__device__ __forceinline__ void ldsm4t(uint32_t* r, uint32_t addr) {
    asm volatile("ldmatrix.sync.aligned.m8n8.x4.trans.shared.b16 {%0,%1,%2,%3}, [%4];"
                 : "=r"(r[0]), "=r"(r[1]), "=r"(r[2]), "=r"(r[3]) : "r"(addr));
}
__device__ __forceinline__ void mma16816(float* d, const uint32_t* a, const uint32_t* b) {
    asm volatile("mma.sync.aligned.m16n8k16.row.col.f32.bf16.bf16.f32 "
                 "{%0,%1,%2,%3}, {%4,%5,%6,%7}, {%8,%9}, {%0,%1,%2,%3};"
                 : "+f"(d[0]), "+f"(d[1]), "+f"(d[2]), "+f"(d[3])
                 : "r"(a[0]), "r"(a[1]), "r"(a[2]), "r"(a[3]), "r"(b[0]), "r"(b[1]));
}

// ===========================================================================
__global__ void k_zero() {
    int i = blockIdx.x * blockDim.x + threadIdx.x;
    if (i < N_E) g_hist[i] = 0;
    if (i == 0)  g_loss = 0.0;
}

__global__ void k_transpose(const float* __restrict__ W) {
    __shared__ float tile[32][33];
    int e0 = blockIdx.x * 32, k0 = blockIdx.y * 32;
    int tx = threadIdx.x, ty = threadIdx.y;
    #pragma unroll
    for (int j = 0; j < 4; j++)
        tile[ty + 8 * j][tx] = W[(size_t)(e0 + ty + 8 * j) * C_DIM + k0 + tx];
    __syncthreads();
    #pragma unroll
    for (int j = 0; j < 4; j++)
        g_Wt[(size_t)(k0 + ty + 8 * j) * N_E + e0 + tx] = tile[tx][ty + 8 * j];
}

// build g_Wb[e][0:256]=hi, [256:512]=lo, [512:768]=hi
__global__ void k_prep(const float* __restrict__ W) {
    int i = blockIdx.x * blockDim.x + threadIdx.x;
    if (i >= N_E * C_DIM) return;
    int e = i >> 8, k = i & 255;
    float w = W[i];
    __nv_bfloat16 hi = __float2bfloat16_rn(w);
    __nv_bfloat16 lo = __float2bfloat16_rn(w - __bfloat162float(hi));
    size_t base = (size_t)e * KP;
    g_Wb[base + k]       = hi;
    g_Wb[base + 256 + k] = lo;
    g_Wb[base + 512 + k] = hi;
}

__global__ void k_znorm(const float* __restrict__ z) {
    int n = blockIdx.x * blockDim.x + threadIdx.x;
    if (n >= N_ROWS) return;
    int b = n >> 10, hw = n & 1023;
    const float* p = z + (size_t)b * C_DIM * HW + hw;
    float s = 0.f;
    #pragma unroll 8
    for (int c = 0; c < C_DIM; c++) { float v = p[(size_t)c * HW]; s += v * v; }
    g_znorm[n] = s;
}

// ===========================================================================
// main: bf16 HMMA argmin.  score = fl(|z|^2 - 2*(z.w)) with 3-pass hi/lo dot
// ===========================================================================
__global__ __launch_bounds__(256, 1)
void k_argmin_mma(const float* __restrict__ z) {
    extern __shared__ char smem[];
    const uint32_t SB = smem_u32(smem);
    int tid = threadIdx.x;
    int L = tid & 31, wid = tid >> 5;
    int mw = wid >> 2, nw = wid & 3;            // warp grid 2(m) x 4(n)
    int s3 = L & 7, b1 = (L >> 3) & 1, b2 = (L >> 4) & 1;
    int koff = s3 + 8 * b2;

    int n0 = blockIdx.x * BM;
    int b  = n0 >> 10;
    int hw0 = n0 & 1023;
    const float* zb = z + (size_t)b * C_DIM * HW + hw0;

    // --- stage A: convert z tile to bf16 hi/lo, k-major [k][128], swizzled ---
    #pragma unroll 4
    for (int i = 0; i < 32; i++) {
        int u = tid + (i << 8);                 // 0..8191 float4 units
        int k = u >> 5;
        int m4 = (u & 31) << 2;
        float4 v = *reinterpret_cast<const float4*>(zb + (size_t)k * HW + m4);
        __nv_bfloat16 h0 = __float2bfloat16_rn(v.x), h1 = __float2bfloat16_rn(v.y);
        __nv_bfloat16 h2 = __float2bfloat16_rn(v.z), h3 = __float2bfloat16_rn(v.w);
        __nv_bfloat16 l0 = __float2bfloat16_rn(v.x - __bfloat162float(h0));
        __nv_bfloat16 l1 = __float2bfloat16_rn(v.y - __bfloat162float(h1));
        __nv_bfloat16 l2 = __float2bfloat16_rn(v.z - __bfloat162float(h2));
        __nv_bfloat16 l3 = __float2bfloat16_rn(v.w - __bfloat162float(h3));
        uint2 hv, lv;
        hv.x = (uint32_t)__bfloat16_as_ushort(h0) | ((uint32_t)__bfloat16_as_ushort(h1) << 16);
        hv.y = (uint32_t)__bfloat16_as_ushort(h2) | ((uint32_t)__bfloat16_as_ushort(h3) << 16);
        lv.x = (uint32_t)__bfloat16_as_ushort(l0) | ((uint32_t)__bfloat16_as_ushort(l1) << 16);
        lv.y = (uint32_t)__bfloat16_as_ushort(l2) | ((uint32_t)__bfloat16_as_ushort(l3) << 16);
        uint32_t c = (uint32_t)(m4 >> 3);
        uint32_t off = (uint32_t)k * 256 + ((c ^ (uint32_t)(k & 7)) << 4) + ((m4 & 7) << 1);
        *reinterpret_cast<uint2*>(smem + A_HI + off) = hv;
        *reinterpret_cast<uint2*>(smem + A_LO + off) = lv;
    }

    // --- per-thread row bookkeeping ---
    int   rloc[8];
    float Arow[8], bestv[8];
    int   besti[8];
    #pragma unroll
    for (int mt = 0; mt < 4; mt++)
        #pragma unroll
        for (int p = 0; p < 2; p++) {
            int q = mt * 2 + p;
            rloc[q] = mw * 64 + mt * 16 + (L >> 2) + 8 * p;
            Arow[q] = g_znorm[n0 + rloc[q]];
            bestv[q] = 3.4e38f; besti[q] = 0;
        }

    // --- precomputed ldmatrix lane offsets ---
    uint32_t aOff[4];
    #pragma unroll
    for (int mt = 0; mt < 4; mt++)
        aOff[mt] = (uint32_t)koff * 256
                 + ((((uint32_t)(mw * 64 + mt * 16) >> 3) + (uint32_t)b1) ^ (uint32_t)s3) * 16;
    uint32_t bRow[2];
    #pragma unroll
    for (int np = 0; np < 2; np++)
        bRow[np] = (uint32_t)(nw * 32 + np * 16 + koff) * 128;

    float acc[4][4][4];
    #pragma unroll
    for (int mt = 0; mt < 4; mt++)
        #pragma unroll
        for (int nt = 0; nt < 4; nt++)
            #pragma unroll
            for (int r = 0; r < 4; r++) acc[mt][nt][r] = 0.f;

    // --- flattened chunk loop: 64 e-tiles x 12 chunks ---
    int e0 = 0, kc = 0;           // current chunk
    int e0n = 0, kcn = 0;         // next chunk (prefetch counters)
    uint4 wreg[4];
    {   // preload chunk 0
        #pragma unroll
        for (int i = 0; i < 4; i++) {
            int u = tid + (i << 8);
            int n = u >> 3, c = u & 7;
            wreg[i] = *reinterpret_cast<const uint4*>(
                &g_Wb[(size_t)n * KP + c * 8]);
        }
    }
    __syncthreads();              // A staged

    #pragma unroll 1
    for (int g = 0; g < NETILE * NCHUNK; g++) {
        uint32_t wb = SB + W_OFF + (uint32_t)(g & 1) * 16384;
        // store prefetched regs -> smem buffer
        #pragma unroll
        for (int i = 0; i < 4; i++) {
            int u = tid + (i << 8);
            int n = u >> 3, c = u & 7;
            uint32_t dst = W_OFF + (uint32_t)(g & 1) * 16384
                         + (uint32_t)n * 128 + (((uint32_t)c ^ (uint32_t)(n & 7)) << 4);
            *reinterpret_cast<uint4*>(smem + dst) = wreg[i];
        }
        __syncthreads();
        // prefetch next chunk
        kcn++; if (kcn == NCHUNK) { kcn = 0; e0n += BM; }
        if (g + 1 < NETILE * NCHUNK) {
            #pragma unroll
            for (int i = 0; i < 4; i++) {
                int u = tid + (i << 8);
                int n = u >> 3, c = u & 7;
                wreg[i] = *reinterpret_cast<const uint4*>(
                    &g_Wb[(size_t)(e0n + n) * KP + kcn * 64 + c * 8]);
            }
        }
        // A smem base for this chunk (hi for k'<512, lo after)
        uint32_t abase = (kc < 8) ? (SB + A_HI + (uint32_t)((kc & 3) * 64) * 256)
                                  : (SB + A_LO + (uint32_t)((kc - 8) * 64) * 256);
        // 4 k16 steps
        #pragma unroll
        for (int s = 0; s < 4; s++) {
            uint32_t a[4][4], bb[2][4];
            uint32_t ab = abase + (uint32_t)(s * 16) * 256;
            #pragma unroll
            for (int mt = 0; mt < 4; mt++) ldsm4t(a[mt], ab + aOff[mt]);
            uint32_t bchnk = ((((uint32_t)(s * 2) + (uint32_t)b1) ^ (uint32_t)s3) << 4);
            #pragma unroll
            for (int np = 0; np < 2; np++) ldsm4(bb[np], wb + bRow[np] + bchnk);
            #pragma unroll
            for (int mt = 0; mt < 4; mt++)
                #pragma unroll
                for (int nt = 0; nt < 4; nt++)
                    mma16816(acc[mt][nt], a[mt], &bb[nt >> 1][(nt & 1) * 2]);
        }
        __syncthreads();          // mma done on buf (g&1) before overwrite at g+2

        kc++;
        if (kc == NCHUNK) {
            // fold e-tile scores into running argmin (register-only)
            #pragma unroll
            for (int mt = 0; mt < 4; mt++)
                #pragma unroll
                for (int nt = 0; nt < 4; nt++) {
                    int c0 = e0 + nw * 32 + nt * 8 + 2 * (L & 3);
                    float s0 = fmaf(-2.0f, acc[mt][nt][0], Arow[mt * 2]);
                    float s1 = fmaf(-2.0f, acc[mt][nt][1], Arow[mt * 2]);
                    float s2 = fmaf(-2.0f, acc[mt][nt][2], Arow[mt * 2 + 1]);
                    float s3v = fmaf(-2.0f, acc[mt][nt][3], Arow[mt * 2 + 1]);
                    if (s0 < bestv[mt * 2])     { bestv[mt * 2] = s0;     besti[mt * 2] = c0; }
                    if (s1 < bestv[mt * 2])     { bestv[mt * 2] = s1;     besti[mt * 2] = c0 + 1; }
                    if (s2 < bestv[mt * 2 + 1]) { bestv[mt * 2 + 1] = s2; besti[mt * 2 + 1] = c0; }
                    if (s3v < bestv[mt * 2 + 1]){ bestv[mt * 2 + 1] = s3v; besti[mt * 2 + 1] = c0 + 1; }
                    acc[mt][nt][0] = 0.f; acc[mt][nt][1] = 0.f;
                    acc[mt][nt][2] = 0.f; acc[mt][nt][3] = 0.f;
                }
            kc = 0; e0 += BM;
        }
    }

    // --- warp-level reduction over the 4 lanes sharing each row ---
    #pragma unroll
    for (int q = 0; q < 8; q++) {
        float v = bestv[q]; int id = besti[q];
        #pragma unroll
        for (int o = 1; o <= 2; o <<= 1) {
            float ov = __shfl_xor_sync(0xFFFFFFFFu, v, o);
            int   oi = __shfl_xor_sync(0xFFFFFFFFu, id, o);
            if (ov < v || (ov == v && oi < id)) { v = ov; id = oi; }
        }
        bestv[q] = v; besti[q] = id;
    }
    __syncthreads();              // W buffers free -> reuse as sred
    float2* sred = reinterpret_cast<float2*>(smem + SRED);
    if ((L & 3) == 0) {
        #pragma unroll
        for (int q = 0; q < 8; q++)
            sred[rloc[q] * 4 + nw] = make_float2(bestv[q], __int_as_float(besti[q]));
    }
    __syncthreads();
    if (tid < BM) {
        float bv = 3.4e38f; int bi = 0;
        #pragma unroll
        for (int w = 0; w < 4; w++) {
            float2 v = sred[tid * 4 + w];
            int id = __float_as_int(v.y);
            if (v.x < bv || (v.x == bv && id < bi)) { bv = v.x; bi = id; }
        }
        g_idx[n0 + tid] = bi;
        atomicAdd(&g_hist[bi], 1);
    }
}

// ===========================================================================
__global__ void k_epilogue(const float* __restrict__ z, float* __restrict__ out) {
    int bid = blockIdx.x;
    int b = bid >> 8, c = bid & 255;
    int tid = threadIdx.x;
    const float* wtc = g_Wt + (size_t)c * N_E;
    float lsum = 0.f;
    #pragma unroll
    for (int it = 0; it < 4; it++) {
        int hw = it * 256 + tid;
        int n  = b * HW + hw;
        int id = g_idx[n];
        float wv = wtc[id];
        size_t off = (size_t)b * C_DIM * HW + (size_t)c * HW + hw;
        float zv = z[off];
        out[off] = wv;
        float d = wv - zv;
        lsum += d * d;
        if (c == 0) out[ZQ_ELEMS + 1 + n] = (float)id;
    }
    __shared__ float red[256];
    red[tid] = lsum;
    __syncthreads();
    for (int s = 128; s; s >>= 1) { if (tid < s) red[tid] += red[tid + s]; __syncthreads(); }
    if (tid == 0) atomicAdd(&g_loss, (double)red[0]);
}

__global__ void k_final(float* __restrict__ out) {
    __shared__ float red[256];
    int tid = threadIdx.x;
    float s = 0.f;
    for (int i = tid; i < N_E; i += 256) {
        float e = (float)g_hist[i] * (1.0f / (float)N_ROWS);
        s += e * logf(e + 1e-10f);
    }
    red[tid] = s;
    __syncthreads();
    for (int st = 128; st; st >>= 1) { if (tid < st) red[tid] += red[tid + st]; __syncthreads(); }
    if (tid == 0) {
        out[ZQ_ELEMS] = 1.25f * (float)(g_loss / (double)ZQ_ELEMS);
        out[ZQ_ELEMS + 1 + N_ROWS] = expf(-red[0]);
    }
}

// ===========================================================================
extern "C" void kernel_launch(void* const* d_in, const int* in_sizes, int n_in,
                              void* d_out, int out_size) {
    const float* z = (const float*)d_in[0];
    const float* W = (const float*)d_in[1];
    float* out = (float*)d_out;

    cudaFuncSetAttribute(k_argmin_mma, cudaFuncAttributeMaxDynamicSharedMemorySize, SMEM_BYTES);

    k_zero<<<(N_E + 255) / 256, 256>>>();
    {
        dim3 g(N_E / 32, C_DIM / 32), blk(32, 8);
        k_transpose<<<g, blk>>>(W);
    }
    k_prep<<<(N_E * C_DIM + 255) / 256, 256>>>(W);
    k_znorm<<<N_ROWS / 256, 256>>>(z);
    k_argmin_mma<<<N_ROWS / BM, 256, SMEM_BYTES>>>(z);
    k_epilogue<<<BATCH * C_DIM, 256>>>(z, out);
    k_final<<<1, 256>>>(out);
}

// round 5
// speedup vs baseline: 3.1016x; 1.1802x over previous
#include <cuda_runtime.h>
#include <cuda_bf16.h>
#include <math.h>
#include <stdint.h>

#define N_E     8192
#define C_DIM   256
#define BATCH   32
#define HW      1024
#define N_ROWS  (BATCH * HW)            // 32768
#define ZQ_ELEMS (BATCH * C_DIM * HW)   // 8388608

#define BM      128                     // rows per CTA
#define KW      512                     // W row: [hi(256) | lo(256)]
#define NKC     4                       // 128-k chunks per e-tile (512/128)
#define NETILE  64                      // e-tiles of 128 codes
#define NITER   (NETILE * NKC)          // 256

// smem offsets (dynamic)
#define A_HI   0                        // [256 k][128 m] bf16 swizzled (64KB)
#define A_LO   65536                    // (64KB)
#define W_OFF  131072                   // 3-stage ring of 32KB chunks
#define CHUNK_BYTES 32768
#define SRED   131072                   // alias of W ring (post-GEMM)
#define SMEM_BYTES (131072 + 3 * CHUNK_BYTES)   // 229376

// ---- scratch (no allocations allowed) ----
__device__ float g_Wt[C_DIM * N_E];                       // Wt[k][e] for epilogue
__device__ __align__(16) __nv_bfloat16 g_Wb[N_E * KW];    // [e][hi|lo]  8.4MB
__device__ float g_znorm[N_ROWS];
__device__ int   g_idx[N_ROWS];
__device__ int   g_hist[N_E];
__device__ double g_loss;

// =========================== helpers ===================================
__device__ __forceinline__ uint32_t smem_u32(const void* p) {
    uint32_t a;
    asm("{ .reg .u64 t; cvta.to.shared.u64 t, %1; cvt.u32.u64 %0, t; }" : "=r"(a) : "l"(p));
    return a;
}
__device__ __forceinline__ void ldsm4(uint32_t* r, uint32_t addr) {
    asm volatile("ldmatrix.sync.aligned.m8n8.x4.shared.b16 {%0,%1,%2,%3}, [%4];"
                 : "=r"(r[0]), "=r"(r[1]), "=r"(r[2]), "=r"(r[3]) : "r"(addr));
}
__device__ __forceinline__ void ldsm4t(uint32_t* r, uint32_t addr) {
    asm volatile("ldmatrix.sync.aligned.m8n8.x4.trans.shared.b16 {%0,%1,%2,%3}, [%4];"
                 : "=r"(r[0]), "=r"(r[1]), "=r"(r[2]), "=r"(r[3]) : "r"(addr));
}
__device__ __forceinline__ void mma16816(float* d, const uint32_t* a, const uint32_t* b) {
    asm volatile("mma.sync.aligned.m16n8k16.row.col.f32.bf16.bf16.f32 "
                 "{%0,%1,%2,%3}, {%4,%5,%6,%7}, {%8,%9}, {%0,%1,%2,%3};"
                 : "+f"(d[0]), "+f"(d[1]), "+f"(d[2]), "+f"(d[3])
                 : "r"(a[0]), "r"(a[1]), "r"(a[2]), "r"(a[3]), "r"(b[0]), "r"(b[1]));
}
__device__ __forceinline__ void cp16(uint32_t dst, const void* src) {
    asm volatile("cp.async.cg.shared.global [%0], [%1], 16;" :: "r"(dst), "l"(src));
}
#define CP_COMMIT() asm volatile("cp.async.commit_group;" ::: "memory")
#define CP_WAIT1()  asm volatile("cp.async.wait_group 1;"  ::: "memory")

// ===========================================================================
__global__ void k_zero() {
    int i = blockIdx.x * blockDim.x + threadIdx.x;
    if (i < N_E) g_hist[i] = 0;
    if (i == 0)  g_loss = 0.0;
}

__global__ void k_transpose(const float* __restrict__ W) {
    __shared__ float tile[32][33];
    int e0 = blockIdx.x * 32, k0 = blockIdx.y * 32;
    int tx = threadIdx.x, ty = threadIdx.y;
    #pragma unroll
    for (int j = 0; j < 4; j++)
        tile[ty + 8 * j][tx] = W[(size_t)(e0 + ty + 8 * j) * C_DIM + k0 + tx];
    __syncthreads();
    #pragma unroll
    for (int j = 0; j < 4; j++)
        g_Wt[(size_t)(k0 + ty + 8 * j) * N_E + e0 + tx] = tile[tx][ty + 8 * j];
}

// build g_Wb[e][0:256]=hi, [256:512]=lo
__global__ void k_prep(const float* __restrict__ W) {
    int i = blockIdx.x * blockDim.x + threadIdx.x;
    if (i >= N_E * C_DIM) return;
    int e = i >> 8, k = i & 255;
    float w = W[i];
    __nv_bfloat16 hi = __float2bfloat16_rn(w);
    __nv_bfloat16 lo = __float2bfloat16_rn(w - __bfloat162float(hi));
    size_t base = (size_t)e * KW;
    g_Wb[base + k]       = hi;
    g_Wb[base + 256 + k] = lo;
}

// |z_n|^2 — sequential over c, identical order to R2/R4 (sets score bins)
__global__ void k_znorm(const float* __restrict__ z) {
    int n = blockIdx.x * blockDim.x + threadIdx.x;
    if (n >= N_ROWS) return;
    int b = n >> 10, hw = n & 1023;
    const float* p = z + (size_t)b * C_DIM * HW + hw;
    float s = 0.f;
    #pragma unroll 8
    for (int c = 0; c < C_DIM; c++) { float v = p[(size_t)c * HW]; s += v * v; }
    g_znorm[n] = s;
}

// ===========================================================================
// main: bf16 HMMA argmin.  score = fl(|z|^2 - 2*(z.w)); dot = hi.hi+hi.lo+lo.hi
// ===========================================================================
__global__ __launch_bounds__(256, 1)
void k_argmin_mma(const float* __restrict__ z) {
    extern __shared__ char smem[];
    const uint32_t SB = smem_u32(smem);
    int tid = threadIdx.x;
    int L = tid & 31, wid = tid >> 5;
    int mw = wid >> 2, nw = wid & 3;            // warp grid 2(m) x 4(n)
    uint32_t s3 = (uint32_t)(L & 7), b1 = (uint32_t)((L >> 3) & 1), b2 = (uint32_t)((L >> 4) & 1);
    uint32_t koff = s3 + 8 * b2;

    int n0 = blockIdx.x * BM;
    int b  = n0 >> 10;
    int hw0 = n0 & 1023;
    const float* zb = z + (size_t)b * C_DIM * HW + hw0;

    // --- issue W chunks 0,1 immediately (overlap with A staging) ---
    auto issue_chunk = [&](int g) {
        int kc = g & 3;
        int e0t = (g >> 2) * BM;
        uint32_t buf = W_OFF + (uint32_t)(g % 3) * CHUNK_BYTES;
        #pragma unroll
        for (int i = 0; i < 8; i++) {
            int u = tid + (i << 8);             // 0..2047 16B-units
            int n = u >> 4, c = u & 15;
            uint32_t dst = SB + buf + (uint32_t)n * 256
                         + (((uint32_t)c ^ (uint32_t)(n & 7)) << 4);
            cp16(dst, &g_Wb[(size_t)(e0t + n) * KW + kc * 128 + c * 8]);
        }
        CP_COMMIT();
    };
    issue_chunk(0);
    issue_chunk(1);

    // --- stage A: z tile -> bf16 hi/lo, k-major [k][128], swizzled ---
    #pragma unroll 4
    for (int i = 0; i < 32; i++) {
        int u = tid + (i << 8);
        int k = u >> 5;
        int m4 = (u & 31) << 2;
        float4 v = *reinterpret_cast<const float4*>(zb + (size_t)k * HW + m4);
        __nv_bfloat16 h0 = __float2bfloat16_rn(v.x), h1 = __float2bfloat16_rn(v.y);
        __nv_bfloat16 h2 = __float2bfloat16_rn(v.z), h3 = __float2bfloat16_rn(v.w);
        __nv_bfloat16 l0 = __float2bfloat16_rn(v.x - __bfloat162float(h0));
        __nv_bfloat16 l1 = __float2bfloat16_rn(v.y - __bfloat162float(h1));
        __nv_bfloat16 l2 = __float2bfloat16_rn(v.z - __bfloat162float(h2));
        __nv_bfloat16 l3 = __float2bfloat16_rn(v.w - __bfloat162float(h3));
        uint2 hv, lv;
        hv.x = (uint32_t)__bfloat16_as_ushort(h0) | ((uint32_t)__bfloat16_as_ushort(h1) << 16);
        hv.y = (uint32_t)__bfloat16_as_ushort(h2) | ((uint32_t)__bfloat16_as_ushort(h3) << 16);
        lv.x = (uint32_t)__bfloat16_as_ushort(l0) | ((uint32_t)__bfloat16_as_ushort(l1) << 16);
        lv.y = (uint32_t)__bfloat16_as_ushort(l2) | ((uint32_t)__bfloat16_as_ushort(l3) << 16);
        uint32_t c = (uint32_t)(m4 >> 3);
        uint32_t off = (uint32_t)k * 256 + ((c ^ (uint32_t)(k & 7)) << 4) + ((m4 & 7) << 1);
        *reinterpret_cast<uint2*>(smem + A_HI + off) = hv;
        *reinterpret_cast<uint2*>(smem + A_LO + off) = lv;
    }

    // --- per-thread row bookkeeping ---
    int   rloc[8];
    float Arow[8], bestv[8];
    int   besti[8];
    #pragma unroll
    for (int mt = 0; mt < 4; mt++)
        #pragma unroll
        for (int p = 0; p < 2; p++) {
            int q = mt * 2 + p;
            rloc[q] = mw * 64 + mt * 16 + (L >> 2) + 8 * p;
            Arow[q] = g_znorm[n0 + rloc[q]];
            bestv[q] = 3.4e38f; besti[q] = 0;
        }

    // --- ldmatrix lane offsets ---
    uint32_t aOff[4];
    #pragma unroll
    for (int mt = 0; mt < 4; mt++)
        aOff[mt] = koff * 256
                 + ((((uint32_t)(mw * 64 + mt * 16) >> 3) + b1) ^ s3) * 16;
    uint32_t bRow[2];
    #pragma unroll
    for (int np = 0; np < 2; np++)
        bRow[np] = (uint32_t)(nw * 32 + np * 16) * 256 + koff * 256;

    float acc[4][4][4];
    #pragma unroll
    for (int mt = 0; mt < 4; mt++)
        #pragma unroll
        for (int nt = 0; nt < 4; nt++)
            #pragma unroll
            for (int r = 0; r < 4; r++) acc[mt][nt][r] = 0.f;

    __syncthreads();              // A staged (cp.async tracked separately)

    #pragma unroll 1
    for (int g = 0; g < NITER; g++) {
        CP_WAIT1();               // chunk g landed
        __syncthreads();          // also proves buf (g+2)%3 reclaimable
        if (g + 2 < NITER) issue_chunk(g + 2);
        else CP_COMMIT();         // keep group accounting uniform

        int kc = g & 3;
        uint32_t wb = SB + W_OFF + (uint32_t)(g % 3) * CHUNK_BYTES;
        // A bases: kc 0,1 -> hi chunk (dual pass); kc 2,3 -> lo W vs A_hi
        uint32_t ab1 = SB + ((kc < 2) ? (A_HI + kc * 32768)
                                      : (A_HI + (kc - 2) * 32768));
        uint32_t ab2 = SB + A_LO + kc * 32768;   // valid only for kc<2

        #pragma unroll 1
        for (int pass = 0; pass < 2; pass++) {
            if (pass == 1 && kc >= 2) break;
            uint32_t abase = (pass == 0) ? ab1 : ab2;
            #pragma unroll
            for (int s = 0; s < 8; s++) {
                uint32_t a[4][4], bb[2][4];
                uint32_t ab = abase + (uint32_t)s * 4096;
                #pragma unroll
                for (int mt = 0; mt < 4; mt++) ldsm4t(a[mt], ab + aOff[mt]);
                uint32_t bco = ((((uint32_t)(s * 2) + b1) ^ s3) << 4);
                #pragma unroll
                for (int np = 0; np < 2; np++) ldsm4(bb[np], wb + bRow[np] + bco);
                #pragma unroll
                for (int mt = 0; mt < 4; mt++)
                    #pragma unroll
                    for (int nt = 0; nt < 4; nt++)
                        mma16816(acc[mt][nt], a[mt], &bb[nt >> 1][(nt & 1) * 2]);
            }
        }

        if (kc == 3) {
            int e0 = (g >> 2) * BM;
            #pragma unroll
            for (int mt = 0; mt < 4; mt++)
                #pragma unroll
                for (int nt = 0; nt < 4; nt++) {
                    int c0 = e0 + nw * 32 + nt * 8 + 2 * (L & 3);
                    float s0 = fmaf(-2.0f, acc[mt][nt][0], Arow[mt * 2]);
                    float s1 = fmaf(-2.0f, acc[mt][nt][1], Arow[mt * 2]);
                    float s2 = fmaf(-2.0f, acc[mt][nt][2], Arow[mt * 2 + 1]);
                    float s3v = fmaf(-2.0f, acc[mt][nt][3], Arow[mt * 2 + 1]);
                    if (s0 < bestv[mt * 2])      { bestv[mt * 2] = s0;      besti[mt * 2] = c0; }
                    if (s1 < bestv[mt * 2])      { bestv[mt * 2] = s1;      besti[mt * 2] = c0 + 1; }
                    if (s2 < bestv[mt * 2 + 1])  { bestv[mt * 2 + 1] = s2;  besti[mt * 2 + 1] = c0; }
                    if (s3v < bestv[mt * 2 + 1]) { bestv[mt * 2 + 1] = s3v; besti[mt * 2 + 1] = c0 + 1; }
                    acc[mt][nt][0] = 0.f; acc[mt][nt][1] = 0.f;
                    acc[mt][nt][2] = 0.f; acc[mt][nt][3] = 0.f;
                }
        }
    }

    // --- reduce over the 4 lanes sharing each row ---
    #pragma unroll
    for (int q = 0; q < 8; q++) {
        float v = bestv[q]; int id = besti[q];
        #pragma unroll
        for (int o = 1; o <= 2; o <<= 1) {
            float ov = __shfl_xor_sync(0xFFFFFFFFu, v, o);
            int   oi = __shfl_xor_sync(0xFFFFFFFFu, id, o);
            if (ov < v || (ov == v && oi < id)) { v = ov; id = oi; }
        }
        bestv[q] = v; besti[q] = id;
    }
    __syncthreads();              // W ring idle -> reuse as sred
    float2* sred = reinterpret_cast<float2*>(smem + SRED);
    if ((L & 3) == 0) {
        #pragma unroll
        for (int q = 0; q < 8; q++)
            sred[rloc[q] * 4 + nw] = make_float2(bestv[q], __int_as_float(besti[q]));
    }
    __syncthreads();
    if (tid < BM) {
        float bv = 3.4e38f; int bi = 0;
        #pragma unroll
        for (int w = 0; w < 4; w++) {
            float2 v = sred[tid * 4 + w];
            int id = __float_as_int(v.y);
            if (v.x < bv || (v.x == bv && id < bi)) { bv = v.x; bi = id; }
        }
        g_idx[n0 + tid] = bi;
        atomicAdd(&g_hist[bi], 1);
    }
}

// ===========================================================================
__global__ void k_epilogue(const float* __restrict__ z, float* __restrict__ out) {
    int bid = blockIdx.x;
    int b = bid >> 8, c = bid & 255;
    int tid = threadIdx.x;
    const float* wtc = g_Wt + (size_t)c * N_E;
    float lsum = 0.f;
    #pragma unroll
    for (int it = 0; it < 4; it++) {
        int hw = it * 256 + tid;
        int n  = b * HW + hw;
        int id = g_idx[n];
        float wv = wtc[id];
        size_t off = (size_t)b * C_DIM * HW + (size_t)c * HW + hw;
        float zv = z[off];
        out[off] = wv;
        float d = wv - zv;
        lsum += d * d;
        if (c == 0) out[ZQ_ELEMS + 1 + n] = (float)id;
    }
    __shared__ float red[256];
    red[tid] = lsum;
    __syncthreads();
    for (int s = 128; s; s >>= 1) { if (tid < s) red[tid] += red[tid + s]; __syncthreads(); }
    if (tid == 0) atomicAdd(&g_loss, (double)red[0]);
}

__global__ void k_final(float* __restrict__ out) {
    __shared__ float red[256];
    int tid = threadIdx.x;
    float s = 0.f;
    for (int i = tid; i < N_E; i += 256) {
        float e = (float)g_hist[i] * (1.0f / (float)N_ROWS);
        s += e * logf(e + 1e-10f);
    }
    red[tid] = s;
    __syncthreads();
    for (int st = 128; st; st >>= 1) { if (tid < st) red[tid] += red[tid + st]; __syncthreads(); }
    if (tid == 0) {
        out[ZQ_ELEMS] = 1.25f * (float)(g_loss / (double)ZQ_ELEMS);
        out[ZQ_ELEMS + 1 + N_ROWS] = expf(-red[0]);
    }
}

// ===========================================================================
extern "C" void kernel_launch(void* const* d_in, const int* in_sizes, int n_in,
                              void* d_out, int out_size) {
    const float* z = (const float*)d_in[0];
    const float* W = (const float*)d_in[1];
    float* out = (float*)d_out;

    cudaFuncSetAttribute(k_argmin_mma, cudaFuncAttributeMaxDynamicSharedMemorySize, SMEM_BYTES);

    k_zero<<<(N_E + 255) / 256, 256>>>();
    {
        dim3 g(N_E / 32, C_DIM / 32), blk(32, 8);
        k_transpose<<<g, blk>>>(W);
    }
    k_prep<<<(N_E * C_DIM + 255) / 256, 256>>>(W);
    k_znorm<<<N_ROWS / 256, 256>>>(z);
    k_argmin_mma<<<N_ROWS / BM, 256, SMEM_BYTES>>>(z);
    k_epilogue<<<BATCH * C_DIM, 256>>>(z, out);
    k_final<<<1, 256>>>(out);
}

// round 6
// speedup vs baseline: 3.2548x; 1.0494x over previous
#include <cuda_runtime.h>
#include <cuda_bf16.h>
#include <math.h>
#include <stdint.h>

#define N_E     8192
#define C_DIM   256
#define BATCH   32
#define HW      1024
#define N_ROWS  (BATCH * HW)            // 32768
#define ZQ_ELEMS (BATCH * C_DIM * HW)   // 8388608

#define BM      128                     // rows per CTA
#define KW      512                     // W row: [hi(256) | lo(256)]
#define NKC     4                       // 128-k chunks per e-tile (512/128)
#define NETILE  64                      // e-tiles of 128 codes
#define NITER   (NETILE * NKC)          // 256

// smem offsets (dynamic)
#define A_HI   0                        // [256 k][128 m] bf16 swizzled (64KB)
#define A_LO   65536                    // (64KB)
#define W_OFF  131072                   // 3-stage ring of 32KB chunks
#define CHUNK_BYTES 32768
#define SRED   131072                   // alias of W ring (post-GEMM)
#define SMEM_BYTES (131072 + 3 * CHUNK_BYTES)   // 229376

// ---- scratch (no allocations allowed) ----
__device__ float g_Wt[C_DIM * N_E];                       // Wt[k][e] for epilogue
__device__ __align__(16) __nv_bfloat16 g_Wb[N_E * KW];    // [e][hi|lo]  8.4MB
__device__ float g_znorm[N_ROWS];
__device__ int   g_idx[N_ROWS];
__device__ int   g_hist[N_E];
__device__ double g_loss;

// =========================== helpers ===================================
__device__ __forceinline__ uint32_t smem_u32(const void* p) {
    uint32_t a;
    asm("{ .reg .u64 t; cvta.to.shared.u64 t, %1; cvt.u32.u64 %0, t; }" : "=r"(a) : "l"(p));
    return a;
}
__device__ __forceinline__ void ldsm4(uint32_t* r, uint32_t addr) {
    asm volatile("ldmatrix.sync.aligned.m8n8.x4.shared.b16 {%0,%1,%2,%3}, [%4];"
                 : "=r"(r[0]), "=r"(r[1]), "=r"(r[2]), "=r"(r[3]) : "r"(addr));
}
__device__ __forceinline__ void ldsm4t(uint32_t* r, uint32_t addr) {
    asm volatile("ldmatrix.sync.aligned.m8n8.x4.trans.shared.b16 {%0,%1,%2,%3}, [%4];"
                 : "=r"(r[0]), "=r"(r[1]), "=r"(r[2]), "=r"(r[3]) : "r"(addr));
}
__device__ __forceinline__ void mma16816(float* d, const uint32_t* a, const uint32_t* b) {
    asm volatile("mma.sync.aligned.m16n8k16.row.col.f32.bf16.bf16.f32 "
                 "{%0,%1,%2,%3}, {%4,%5,%6,%7}, {%8,%9}, {%0,%1,%2,%3};"
                 : "+f"(d[0]), "+f"(d[1]), "+f"(d[2]), "+f"(d[3])
                 : "r"(a[0]), "r"(a[1]), "r"(a[2]), "r"(a[3]), "r"(b[0]), "r"(b[1]));
}
__device__ __forceinline__ void cp16(uint32_t dst, const void* src) {
    asm volatile("cp.async.cg.shared.global [%0], [%1], 16;" :: "r"(dst), "l"(src));
}
#define CP_COMMIT() asm volatile("cp.async.commit_group;" ::: "memory")
#define CP_WAIT1()  asm volatile("cp.async.wait_group 1;"  ::: "memory")

// ===========================================================================
// 1) per-launch zeroing
__global__ void k_zero() {
    int i = blockIdx.x * blockDim.x + threadIdx.x;
    if (i < N_E) g_hist[i] = 0;
    if (i == 0)  g_loss = 0.0;
}

// 2) fused: W -> Wt (transpose, for epilogue) + hi/lo bf16 split (for GEMM).
//    Reads W exactly once.  grid (E/32, C/32), block (32, 8)
__global__ void k_wprep(const float* __restrict__ W) {
    __shared__ float tile[32][33];
    int e0 = blockIdx.x * 32, k0 = blockIdx.y * 32;
    int tx = threadIdx.x, ty = threadIdx.y;
    #pragma unroll
    for (int j = 0; j < 4; j++) {
        int e = e0 + ty + 8 * j;
        int k = k0 + tx;
        float w = W[(size_t)e * C_DIM + k];
        tile[ty + 8 * j][tx] = w;
        __nv_bfloat16 hi = __float2bfloat16_rn(w);
        __nv_bfloat16 lo = __float2bfloat16_rn(w - __bfloat162float(hi));
        size_t base = (size_t)e * KW;
        g_Wb[base + k]       = hi;
        g_Wb[base + 256 + k] = lo;
    }
    __syncthreads();
    #pragma unroll
    for (int j = 0; j < 4; j++)
        g_Wt[(size_t)(k0 + ty + 8 * j) * N_E + e0 + tx] = tile[tx][ty + 8 * j];
}

// 3) |z_n|^2 — sequential over c, identical order since R2 (sets score bins)
__global__ void k_znorm(const float* __restrict__ z) {
    int n = blockIdx.x * blockDim.x + threadIdx.x;
    if (n >= N_ROWS) return;
    int b = n >> 10, hw = n & 1023;
    const float* p = z + (size_t)b * C_DIM * HW + hw;
    float s = 0.f;
    #pragma unroll 8
    for (int c = 0; c < C_DIM; c++) { float v = p[(size_t)c * HW]; s += v * v; }
    g_znorm[n] = s;
}

// ===========================================================================
// 4) main: bf16 HMMA argmin.  score = fl(|z|^2 - 2*(z.w));
//    dot = hi.hi + lo.hi (interleaved per step) + hi.lo
// ===========================================================================
__global__ __launch_bounds__(256, 1)
void k_argmin_mma(const float* __restrict__ z) {
    extern __shared__ char smem[];
    const uint32_t SB = smem_u32(smem);
    int tid = threadIdx.x;
    int L = tid & 31, wid = tid >> 5;
    int mw = wid >> 2, nw = wid & 3;            // warp grid 2(m) x 4(n)
    uint32_t s3 = (uint32_t)(L & 7), b1 = (uint32_t)((L >> 3) & 1), b2 = (uint32_t)((L >> 4) & 1);
    uint32_t koff = s3 + 8 * b2;

    int n0 = blockIdx.x * BM;
    int b  = n0 >> 10;
    int hw0 = n0 & 1023;
    const float* zb = z + (size_t)b * C_DIM * HW + hw0;

    // --- issue W chunks 0,1 immediately (overlap with A staging) ---
    auto issue_chunk = [&](int g) {
        int kc = g & 3;
        int e0t = (g >> 2) * BM;
        uint32_t buf = W_OFF + (uint32_t)(g % 3) * CHUNK_BYTES;
        #pragma unroll
        for (int i = 0; i < 8; i++) {
            int u = tid + (i << 8);             // 0..2047 16B-units
            int n = u >> 4, c = u & 15;
            uint32_t dst = SB + buf + (uint32_t)n * 256
                         + (((uint32_t)c ^ (uint32_t)(n & 7)) << 4);
            cp16(dst, &g_Wb[(size_t)(e0t + n) * KW + kc * 128 + c * 8]);
        }
        CP_COMMIT();
    };
    issue_chunk(0);
    issue_chunk(1);

    // --- stage A: z tile -> bf16 hi/lo, k-major [k][128], swizzled ---
    #pragma unroll 4
    for (int i = 0; i < 32; i++) {
        int u = tid + (i << 8);
        int k = u >> 5;
        int m4 = (u & 31) << 2;
        float4 v = *reinterpret_cast<const float4*>(zb + (size_t)k * HW + m4);
        __nv_bfloat16 h0 = __float2bfloat16_rn(v.x), h1 = __float2bfloat16_rn(v.y);
        __nv_bfloat16 h2 = __float2bfloat16_rn(v.z), h3 = __float2bfloat16_rn(v.w);
        __nv_bfloat16 l0 = __float2bfloat16_rn(v.x - __bfloat162float(h0));
        __nv_bfloat16 l1 = __float2bfloat16_rn(v.y - __bfloat162float(h1));
        __nv_bfloat16 l2 = __float2bfloat16_rn(v.z - __bfloat162float(h2));
        __nv_bfloat16 l3 = __float2bfloat16_rn(v.w - __bfloat162float(h3));
        uint2 hv, lv;
        hv.x = (uint32_t)__bfloat16_as_ushort(h0) | ((uint32_t)__bfloat16_as_ushort(h1) << 16);
        hv.y = (uint32_t)__bfloat16_as_ushort(h2) | ((uint32_t)__bfloat16_as_ushort(h3) << 16);
        lv.x = (uint32_t)__bfloat16_as_ushort(l0) | ((uint32_t)__bfloat16_as_ushort(l1) << 16);
        lv.y = (uint32_t)__bfloat16_as_ushort(l2) | ((uint32_t)__bfloat16_as_ushort(l3) << 16);
        uint32_t c = (uint32_t)(m4 >> 3);
        uint32_t off = (uint32_t)k * 256 + ((c ^ (uint32_t)(k & 7)) << 4) + ((m4 & 7) << 1);
        *reinterpret_cast<uint2*>(smem + A_HI + off) = hv;
        *reinterpret_cast<uint2*>(smem + A_LO + off) = lv;
    }

    // --- per-thread row bookkeeping ---
    int   rloc[8];
    float Arow[8], bestv[8];
    int   besti[8];
    #pragma unroll
    for (int mt = 0; mt < 4; mt++)
        #pragma unroll
        for (int p = 0; p < 2; p++) {
            int q = mt * 2 + p;
            rloc[q] = mw * 64 + mt * 16 + (L >> 2) + 8 * p;
            Arow[q] = g_znorm[n0 + rloc[q]];
            bestv[q] = 3.4e38f; besti[q] = 0;
        }

    // --- ldmatrix lane offsets ---
    uint32_t aOff[4];
    #pragma unroll
    for (int mt = 0; mt < 4; mt++)
        aOff[mt] = koff * 256
                 + ((((uint32_t)(mw * 64 + mt * 16) >> 3) + b1) ^ s3) * 16;
    uint32_t bRow[2];
    #pragma unroll
    for (int np = 0; np < 2; np++)
        bRow[np] = (uint32_t)(nw * 32 + np * 16) * 256 + koff * 256;

    float acc[4][4][4];
    #pragma unroll
    for (int mt = 0; mt < 4; mt++)
        #pragma unroll
        for (int nt = 0; nt < 4; nt++)
            #pragma unroll
            for (int r = 0; r < 4; r++) acc[mt][nt][r] = 0.f;

    __syncthreads();              // A staged (cp.async tracked separately)

    #pragma unroll 1
    for (int g = 0; g < NITER; g++) {
        CP_WAIT1();               // chunk g landed
        __syncthreads();          // also proves buf (g+2)%3 reclaimable
        if (g + 2 < NITER) issue_chunk(g + 2);
        else CP_COMMIT();         // keep group accounting uniform

        int kc = g & 3;
        uint32_t wb = SB + W_OFF + (uint32_t)(g % 3) * CHUNK_BYTES;
        bool hiW = (kc < 2);
        uint32_t abHI = SB + A_HI + (hiW ? kc : (kc - 2)) * 32768;
        uint32_t abLO = SB + A_LO + kc * 32768;          // valid only if hiW

        #pragma unroll
        for (int s = 0; s < 8; s++) {
            uint32_t a[4][4], bb[2][4];
            uint32_t bco = ((((uint32_t)(s * 2) + b1) ^ s3) << 4);
            #pragma unroll
            for (int np = 0; np < 2; np++) ldsm4(bb[np], wb + bRow[np] + bco);
            uint32_t abh = abHI + (uint32_t)s * 4096;
            #pragma unroll
            for (int mt = 0; mt < 4; mt++) ldsm4t(a[mt], abh + aOff[mt]);
            #pragma unroll
            for (int mt = 0; mt < 4; mt++)
                #pragma unroll
                for (int nt = 0; nt < 4; nt++)
                    mma16816(acc[mt][nt], a[mt], &bb[nt >> 1][(nt & 1) * 2]);
            if (hiW) {            // second A pass reusing W fragments
                uint32_t abl = abLO + (uint32_t)s * 4096;
                #pragma unroll
                for (int mt = 0; mt < 4; mt++) ldsm4t(a[mt], abl + aOff[mt]);
                #pragma unroll
                for (int mt = 0; mt < 4; mt++)
                    #pragma unroll
                    for (int nt = 0; nt < 4; nt++)
                        mma16816(acc[mt][nt], a[mt], &bb[nt >> 1][(nt & 1) * 2]);
            }
        }

        if (kc == 3) {
            int e0 = (g >> 2) * BM;
            #pragma unroll
            for (int mt = 0; mt < 4; mt++)
                #pragma unroll
                for (int nt = 0; nt < 4; nt++) {
                    int c0 = e0 + nw * 32 + nt * 8 + 2 * (L & 3);
                    float s0 = fmaf(-2.0f, acc[mt][nt][0], Arow[mt * 2]);
                    float s1 = fmaf(-2.0f, acc[mt][nt][1], Arow[mt * 2]);
                    float s2 = fmaf(-2.0f, acc[mt][nt][2], Arow[mt * 2 + 1]);
                    float s3v = fmaf(-2.0f, acc[mt][nt][3], Arow[mt * 2 + 1]);
                    if (s0 < bestv[mt * 2])      { bestv[mt * 2] = s0;      besti[mt * 2] = c0; }
                    if (s1 < bestv[mt * 2])      { bestv[mt * 2] = s1;      besti[mt * 2] = c0 + 1; }
                    if (s2 < bestv[mt * 2 + 1])  { bestv[mt * 2 + 1] = s2;  besti[mt * 2 + 1] = c0; }
                    if (s3v < bestv[mt * 2 + 1]) { bestv[mt * 2 + 1] = s3v; besti[mt * 2 + 1] = c0 + 1; }
                    acc[mt][nt][0] = 0.f; acc[mt][nt][1] = 0.f;
                    acc[mt][nt][2] = 0.f; acc[mt][nt][3] = 0.f;
                }
        }
    }

    // --- reduce over the 4 lanes sharing each row ---
    #pragma unroll
    for (int q = 0; q < 8; q++) {
        float v = bestv[q]; int id = besti[q];
        #pragma unroll
        for (int o = 1; o <= 2; o <<= 1) {
            float ov = __shfl_xor_sync(0xFFFFFFFFu, v, o);
            int   oi = __shfl_xor_sync(0xFFFFFFFFu, id, o);
            if (ov < v || (ov == v && oi < id)) { v = ov; id = oi; }
        }
        bestv[q] = v; besti[q] = id;
    }
    __syncthreads();              // W ring idle -> reuse as sred
    float2* sred = reinterpret_cast<float2*>(smem + SRED);
    if ((L & 3) == 0) {
        #pragma unroll
        for (int q = 0; q < 8; q++)
            sred[rloc[q] * 4 + nw] = make_float2(bestv[q], __int_as_float(besti[q]));
    }
    __syncthreads();
    if (tid < BM) {
        float bv = 3.4e38f; int bi = 0;
        #pragma unroll
        for (int w = 0; w < 4; w++) {
            float2 v = sred[tid * 4 + w];
            int id = __float_as_int(v.y);
            if (v.x < bv || (v.x == bv && id < bi)) { bv = v.x; bi = id; }
        }
        g_idx[n0 + tid] = bi;
        atomicAdd(&g_hist[bi], 1);
    }
}

// ===========================================================================
// 5) epilogue: z_q gather, loss partials, index output
__global__ void k_epilogue(const float* __restrict__ z, float* __restrict__ out) {
    int bid = blockIdx.x;
    int b = bid >> 8, c = bid & 255;
    int tid = threadIdx.x;
    const float* wtc = g_Wt + (size_t)c * N_E;
    float lsum = 0.f;
    #pragma unroll
    for (int it = 0; it < 4; it++) {
        int hw = it * 256 + tid;
        int n  = b * HW + hw;
        int id = g_idx[n];
        float wv = wtc[id];
        size_t off = (size_t)b * C_DIM * HW + (size_t)c * HW + hw;
        float zv = z[off];
        out[off] = wv;
        float d = wv - zv;
        lsum += d * d;
        if (c == 0) out[ZQ_ELEMS + 1 + n] = (float)id;
    }
    __shared__ float red[256];
    red[tid] = lsum;
    __syncthreads();
    for (int s = 128; s; s >>= 1) { if (tid < s) red[tid] += red[tid + s]; __syncthreads(); }
    if (tid == 0) atomicAdd(&g_loss, (double)red[0]);
}

// 6) final scalars
__global__ void k_final(float* __restrict__ out) {
    __shared__ float red[256];
    int tid = threadIdx.x;
    float s = 0.f;
    for (int i = tid; i < N_E; i += 256) {
        float e = (float)g_hist[i] * (1.0f / (float)N_ROWS);
        s += e * logf(e + 1e-10f);
    }
    red[tid] = s;
    __syncthreads();
    for (int st = 128; st; st >>= 1) { if (tid < st) red[tid] += red[tid + st]; __syncthreads(); }
    if (tid == 0) {
        out[ZQ_ELEMS] = 1.25f * (float)(g_loss / (double)ZQ_ELEMS);
        out[ZQ_ELEMS + 1 + N_ROWS] = expf(-red[0]);
    }
}

// ===========================================================================
extern "C" void kernel_launch(void* const* d_in, const int* in_sizes, int n_in,
                              void* d_out, int out_size) {
    const float* z = (const float*)d_in[0];
    const float* W = (const float*)d_in[1];
    float* out = (float*)d_out;

    cudaFuncSetAttribute(k_argmin_mma, cudaFuncAttributeMaxDynamicSharedMemorySize, SMEM_BYTES);

    k_zero<<<(N_E + 255) / 256, 256>>>();                       // launch 1
    {
        dim3 g(N_E / 32, C_DIM / 32), blk(32, 8);
        k_wprep<<<g, blk>>>(W);                                 // launch 2
    }
    k_znorm<<<N_ROWS / 256, 256>>>(z);                          // launch 3
    k_argmin_mma<<<N_ROWS / BM, 256, SMEM_BYTES>>>(z);          // launch 4 (ncu slot)
    k_epilogue<<<BATCH * C_DIM, 256>>>(z, out);                 // launch 5
    k_final<<<1, 256>>>(out);                                   // launch 6
}